// round 14
// baseline (speedup 1.0000x reference)
#include <cuda_runtime.h>
#include <cuda_fp16.h>
#include <math.h>
#include <cstdint>

#define NB    2
#define LQ    4096
#define NHEAD 12
#define DH    64
#define HDIM  768
#define NLROWS (NB*LQ)     // 8192
#define NHTOT  (NB*NHEAD)  // 24
#define QKVS  ((size_t)NHTOT * LQ * DH)
#define WSZ   (HDIM * HDIM)                // 589824
#define XN    (NLROWS * HDIM)              // 6291456

// Scratch (device globals: allocation-free rule)
__device__ __half g_xh [(size_t)XN];               // x in fp16
__device__ __half g_wh [4 * (size_t)WSZ];          // Wq(scaled),Wk,Wv,Wo fp16
__device__ __half g_qkv[3 * QKVS];                 // [qkv][nh][l][d] fp16
__device__ __half g_ctxh[(size_t)NLROWS * HDIM];   // attention output fp16

#define QSCALE (0.125f * 1.44269504088896340736f)  // 1/sqrt(D) * log2(e)

// ---------------------------------------------------------------------------
// helpers
// ---------------------------------------------------------------------------
__device__ __forceinline__ uint32_t smem_u32(const void* p) {
    uint32_t a;
    asm("{ .reg .u64 t; cvta.to.shared.u64 t, %1; cvt.u32.u64 %0, t; }"
        : "=r"(a) : "l"(p));
    return a;
}
__device__ __forceinline__ float ex2f(float x) {
    float r; asm("ex2.approx.ftz.f32 %0, %1;" : "=f"(r) : "f"(x)); return r;
}
__device__ __forceinline__ uint32_t h2pack(float lo, float hi) {
    uint32_t u;
    asm("cvt.rn.f16x2.f32 %0, %1, %2;" : "=r"(u) : "f"(hi), "f"(lo));
    return u;
}
__device__ __forceinline__ void mma16(float* c, const uint32_t* a, const uint32_t* b) {
    asm volatile(
        "mma.sync.aligned.m16n8k16.row.col.f32.f16.f16.f32 "
        "{%0,%1,%2,%3}, {%4,%5,%6,%7}, {%8,%9}, {%0,%1,%2,%3};"
        : "+f"(c[0]), "+f"(c[1]), "+f"(c[2]), "+f"(c[3])
        : "r"(a[0]), "r"(a[1]), "r"(a[2]), "r"(a[3]), "r"(b[0]), "r"(b[1]));
}
__device__ __forceinline__ void ldmx4(uint32_t* r, uint32_t addr) {
    asm volatile("ldmatrix.sync.aligned.m8n8.x4.shared.b16 {%0,%1,%2,%3}, [%4];"
        : "=r"(r[0]), "=r"(r[1]), "=r"(r[2]), "=r"(r[3]) : "r"(addr));
}
__device__ __forceinline__ void ldmx4t(uint32_t* r, uint32_t addr) {
    asm volatile("ldmatrix.sync.aligned.m8n8.x4.trans.shared.b16 {%0,%1,%2,%3}, [%4];"
        : "=r"(r[0]), "=r"(r[1]), "=r"(r[2]), "=r"(r[3]) : "r"(addr));
}
__device__ __forceinline__ void cp16(uint32_t dst, const void* src) {
    asm volatile("cp.async.cg.shared.global [%0], [%1], 16;"
        :: "r"(dst), "l"(src) : "memory");
}
__device__ __forceinline__ void cp_commit() {
    asm volatile("cp.async.commit_group;" ::: "memory");
}
template<int N> __device__ __forceinline__ void cp_wait() {
    asm volatile("cp.async.wait_group %0;" :: "n"(N) : "memory");
}

// ===========================================================================
// Fused fp32->fp16 convert of all 5 tensors in ONE launch.
// ===========================================================================
__global__ void f2h_all(
    const float* __restrict__ x,  const float* __restrict__ Wq,
    const float* __restrict__ Wk, const float* __restrict__ Wv,
    const float* __restrict__ Wo, __half* __restrict__ xh,
    __half* __restrict__ wh)
{
    size_t i = ((size_t)blockIdx.x * blockDim.x + threadIdx.x) * 4;
    const float* src; __half* dst; float sc = 1.0f; size_t off;
    if (i < (size_t)XN) {
        src = x; dst = xh; off = i;
    } else {
        size_t j = i - XN;
        int w = (int)(j / WSZ);
        off = j - (size_t)w * WSZ;
        dst = wh + (size_t)w * WSZ;
        src = (w == 0) ? Wq : (w == 1) ? Wk : (w == 2) ? Wv : Wo;
        if (w == 0) sc = QSCALE;
    }
    float4 v = *(const float4*)(src + off);
    *(__half2*)(dst + off)     = __floats2half2_rn(v.x * sc, v.y * sc);
    *(__half2*)(dst + off + 2) = __floats2half2_rn(v.z * sc, v.w * sc);
}

// ===========================================================================
// fp16 GEMM, occupancy-reshaped: CTA = 128 thr (4 warps), tile 128x64,
// K-chunk 32, 3-stage cp.async ring (prefetch AFTER compute), ldmatrix.
// 4 CTAs/SM (reg-limited) -> each SMSP holds warps of 4 DIFFERENT CTAs, so
// barriers/cp_wait never convoy more than 1/4 of an SMSP's warps (this is
// the attention kernel's occupancy shape, which sustains 290 TF/s).
// Per warp: 32 rows x 64 cols output (C[2][8][4]), 32 mma + 12 ldmatrix/iter.
// Smem/buf: A [128 rows][80B] + W [32 rows][144B] = 14848 B; x3 = 44544 B.
// ===========================================================================
#define GA_BYTES (128 * 80)                 // 10240
#define GW_BYTES (32 * 144)                 // 4608
#define GBUFB    (GA_BYTES + GW_BYTES)      // 14848
#define GEMM_SMEM (3 * GBUFB)               // 44544

template<int MODE>
__global__ __launch_bounds__(128) void gemm_tc(
    const __half* __restrict__ A, const __half* __restrict__ Whbase,
    const float* __restrict__ b0, const float* __restrict__ b1,
    const float* __restrict__ b2, void* __restrict__ outv)
{
    extern __shared__ char smc[];
    const uint32_t sb0 = smem_u32(smc);
    const int z = (MODE == 0) ? blockIdx.z : 0;
    const __half* W = Whbase + (size_t)z * WSZ;
    const float* bias = (z == 0) ? b0 : (z == 1) ? b1 : b2;
    const float bsc = (MODE == 0 && z == 0) ? QSCALE : 1.0f;

    const int tid = threadIdx.x;
    const int lane = tid & 31;
    const int q  = lane >> 2, c4 = lane & 3;
    const int wid = tid >> 5;                 // 0..3, m-strip
    const int row0 = blockIdx.y << 7;
    const int col0 = blockIdx.x << 6;         // 64-col tiles

    // cp.async staging: A = 1 row/thread (4x cp16 covers 32 fp16);
    //                   W = quarter-row/thread (2x cp16 covers 16 fp16)
    const __half* asrc0 = A + (size_t)(row0 + tid) * HDIM;
    const uint32_t adst0 = tid * 80;
    const int wr = tid >> 2, wq = tid & 3;
    const __half* wsrc0 = W + (size_t)wr * HDIM + col0 + wq * 16;
    const uint32_t wdst0 = GA_BYTES + wr * 144 + wq * 32;

    // ldmatrix per-thread address pieces
    const uint32_t a_off = (uint32_t)((wid * 32 + (lane & 15)) * 80 + (lane >> 4) * 16);
    const uint32_t w_off = (uint32_t)(GA_BYTES + (lane & 15) * 144 + (lane >> 4) * 16);

    float C[2][8][4] = {};

    // pre-issue chunks 0 and 1 into buffers 0 and 1
#pragma unroll
    for (int c = 0; c < 2; c++) {
        uint32_t bb = sb0 + c * GBUFB;
        const __half* as = asrc0 + c * 32;
        const __half* ws = wsrc0 + (size_t)(c * 32) * HDIM;
#pragma unroll
        for (int i = 0; i < 4; i++) cp16(bb + adst0 + i * 16, as + i * 8);
        cp16(bb + wdst0, ws); cp16(bb + wdst0 + 16, ws + 8);
        cp_commit();
    }

    int bcur = 0;
    for (int c = 0; c < 24; c++) {
        if (c < 23) cp_wait<1>(); else cp_wait<0>();
        __syncthreads();

        const uint32_t sb = sb0 + bcur * GBUFB;
#pragma unroll
        for (int s = 0; s < 2; s++) {
            uint32_t a[2][4];
            ldmx4(a[0], sb + a_off + s * 32);
            ldmx4(a[1], sb + a_off + 16 * 80 + s * 32);
#pragma unroll
            for (int nj = 0; nj < 4; nj++) {
                uint32_t b[4];
                ldmx4t(b, sb + w_off + (s * 16) * 144 + nj * 32);
                mma16(C[0][2*nj],   a[0], &b[0]);
                mma16(C[0][2*nj+1], a[0], &b[2]);
                mma16(C[1][2*nj],   a[1], &b[0]);
                mma16(C[1][2*nj+1], a[1], &b[2]);
            }
        }

        // issue chunk c+2 into buffer (bcur+2)%3 (readers passed barrier)
        if (c < 22) {
            int bn = bcur + 2; if (bn >= 3) bn -= 3;
            int k0 = (c + 2) * 32;
            uint32_t bb = sb0 + bn * GBUFB;
            const __half* as = asrc0 + k0;
            const __half* ws = wsrc0 + (size_t)k0 * HDIM;
#pragma unroll
            for (int i = 0; i < 4; i++) cp16(bb + adst0 + i * 16, as + i * 8);
            cp16(bb + wdst0, ws); cp16(bb + wdst0 + 16, ws + 8);
            cp_commit();
        }
        if (++bcur == 3) bcur = 0;
    }

    // ---- epilogue ----
#pragma unroll
    for (int mt = 0; mt < 2; mt++) {
#pragma unroll
        for (int nt = 0; nt < 8; nt++) {
            int r  = row0 + wid * 32 + mt * 16 + q;
            int cc = col0 + nt * 8 + 2 * c4;
            float2 bv = *(const float2*)(bias + cc);
            float o00 = C[mt][nt][0] + bv.x * bsc;
            float o01 = C[mt][nt][1] + bv.y * bsc;
            float o10 = C[mt][nt][2] + bv.x * bsc;
            float o11 = C[mt][nt][3] + bv.y * bsc;
            if (MODE == 0) {
                __half* dst = (__half*)outv + (size_t)z * QKVS;
                int h_ = cc >> 6, d_ = cc & 63;
                int n0 = r >> 12, l0 = r & 4095;
                int n1 = (r + 8) >> 12, l1 = (r + 8) & 4095;
                *(__half2*)(dst + ((size_t)(n0 * NHEAD + h_) * LQ + l0) * DH + d_) =
                    __floats2half2_rn(o00, o01);
                *(__half2*)(dst + ((size_t)(n1 * NHEAD + h_) * LQ + l1) * DH + d_) =
                    __floats2half2_rn(o10, o11);
            } else {
                float* dst = (float*)outv;
                *(float2*)(dst + (size_t)r * HDIM + cc) = make_float2(o00, o01);
                *(float2*)(dst + (size_t)(r + 8) * HDIM + cc) = make_float2(o10, o11);
            }
        }
    }
}

// ===========================================================================
// fp16 flash attention — EXACT R9 structure (best measured: ~355us).
// CTA: 128 thr (4 warps), Q tile 128 (32 rows/warp), key tiles 64 in two
// 32-key halves. P stays in registers (S C-frags -> PV A-frags).
// cp.async 3-buffer ring, ONE __syncthreads per tile.
// ===========================================================================
#define AK_BYTES (64 * 144)                  // 9216
#define ABUFB    (2 * AK_BYTES)              // 18432
#define ATTN_SMEM (3 * ABUFB)                // 55296

__global__ __launch_bounds__(128) void attn_mma(
    const __half* __restrict__ gq, const __half* __restrict__ gk,
    const __half* __restrict__ gv, __half* __restrict__ gctx)
{
    extern __shared__ char smc[];
    const uint32_t sb0 = smem_u32(smc);
    const int tid = threadIdx.x;
    const int lane = tid & 31;
    const int q  = lane >> 2, c4 = lane & 3;
    const int wid = tid >> 5;
    const int wm = wid * 32;
    const int nh = blockIdx.y;
    const int n_ = nh / NHEAD, h_ = nh % NHEAD;
    const int q0 = blockIdx.x << 7;
    const size_t base = (size_t)nh * LQ * DH;

    // ldmatrix address pieces
    const uint32_t krow8  = (uint32_t)((lane & 7) + (lane >> 4) * 8);   // K (non-trans B)
    const uint32_t koff16 = (uint32_t)(((lane >> 3) & 1) * 16);
    const uint32_t vrow   = (uint32_t)(lane & 15);                      // V (trans B) / Q (A)
    const uint32_t voff16 = (uint32_t)((lane >> 4) * 16);

    // cp.async staging: thread -> 4 K chunks + 4 V chunks
    const int sr = tid & 63, scb = (tid >> 6) * 4;
    const uint32_t kdst0 = sr * 144 + scb * 16;

    // ---- stage Q via cp.async into buffer-2 region, preload Q fragments ----
    {
        const __half* src = gq + base + (size_t)(q0 + tid) * DH;
        uint32_t dst = sb0 + 2 * ABUFB + tid * 144;
#pragma unroll
        for (int i = 0; i < 8; i++) cp16(dst + i * 16, src + i * 8);
        cp_commit();
        cp_wait<0>();
    }
    __syncthreads();
    uint32_t Qf[2][4][4];
#pragma unroll
    for (int mt = 0; mt < 2; mt++)
#pragma unroll
        for (int s = 0; s < 4; s++)
            ldmx4(Qf[mt][s], sb0 + 2 * ABUFB + (wm + mt * 16 + vrow) * 144 +
                             s * 32 + voff16);

    // pre-issue tiles 0 and 1 into buffers 0 and 1
#pragma unroll
    for (int t = 0; t < 2; t++) {
        const __half* ks = gk + base + (size_t)(t * 64 + sr) * DH + scb * 8;
        const __half* vs = gv + base + (size_t)(t * 64 + sr) * DH + scb * 8;
        uint32_t kd = sb0 + t * ABUFB + kdst0;
#pragma unroll
        for (int i = 0; i < 4; i++) cp16(kd + i * 16, ks + i * 8);
#pragma unroll
        for (int i = 0; i < 4; i++) cp16(kd + AK_BYTES + i * 16, vs + i * 8);
        cp_commit();
    }

#define ATTN_HALF(hh)                                                         \
    {                                                                         \
        float S[2][4][4] = {};                                                \
        _Pragma("unroll")                                                     \
        for (int s = 0; s < 4; s++) {                                         \
            _Pragma("unroll")                                                 \
            for (int g = 0; g < 2; g++) {                                     \
                uint32_t t[4];                                                \
                ldmx4(t, kb + ((hh)*32 + g*16 + krow8) * 144 + s*32 + koff16);\
                mma16(S[0][2*g],   Qf[0][s], &t[0]);                          \
                mma16(S[0][2*g+1], Qf[0][s], &t[2]);                          \
                mma16(S[1][2*g],   Qf[1][s], &t[0]);                          \
                mma16(S[1][2*g+1], Qf[1][s], &t[2]);                          \
            }                                                                 \
        }                                                                     \
        uint32_t P[2][2][4];                                                  \
        _Pragma("unroll")                                                     \
        for (int mt = 0; mt < 2; mt++) {                                      \
            _Pragma("unroll")                                                 \
            for (int ks = 0; ks < 2; ks++) {                                  \
                float e0 = ex2f(S[mt][2*ks][0]),  e1 = ex2f(S[mt][2*ks][1]);  \
                float e2 = ex2f(S[mt][2*ks][2]),  e3 = ex2f(S[mt][2*ks][3]);  \
                float f0 = ex2f(S[mt][2*ks+1][0]), f1 = ex2f(S[mt][2*ks+1][1]);\
                float f2 = ex2f(S[mt][2*ks+1][2]), f3 = ex2f(S[mt][2*ks+1][3]);\
                acc[mt][0] += (e0 + e1) + (f0 + f1);                          \
                acc[mt][1] += (e2 + e3) + (f2 + f3);                          \
                P[mt][ks][0] = h2pack(e0, e1);                                \
                P[mt][ks][1] = h2pack(e2, e3);                                \
                P[mt][ks][2] = h2pack(f0, f1);                                \
                P[mt][ks][3] = h2pack(f2, f3);                                \
            }                                                                 \
        }                                                                     \
        _Pragma("unroll")                                                     \
        for (int ks = 0; ks < 2; ks++) {                                      \
            _Pragma("unroll")                                                 \
            for (int nj = 0; nj < 4; nj++) {                                  \
                uint32_t t[4];                                                \
                ldmx4t(t, vb + ((hh)*32 + ks*16 + vrow) * 144 + nj*32 + voff16);\
                mma16(O[0][2*nj],   P[0][ks], &t[0]);                         \
                mma16(O[0][2*nj+1], P[0][ks], &t[2]);                         \
                mma16(O[1][2*nj],   P[1][ks], &t[0]);                         \
                mma16(O[1][2*nj+1], P[1][ks], &t[2]);                         \
            }                                                                 \
        }                                                                     \
    }

    float O[2][8][4] = {};
    float acc[2][2] = {};

    for (int j = 0; j < LQ / 64; j++) {
        if (j < LQ / 64 - 1) cp_wait<1>(); else cp_wait<0>();
        __syncthreads();

        const uint32_t kb = sb0 + (j % 3) * ABUFB;
        const uint32_t vb = kb + AK_BYTES;
        ATTN_HALF(0)
        ATTN_HALF(1)

        // issue tile j+2 into buffer (j+2)%3 (safe: barrier above)
        if (j < LQ / 64 - 2) {
            int bn = (j + 2) % 3;
            const __half* ks = gk + base + (size_t)((j + 2) * 64 + sr) * DH + scb * 8;
            const __half* vs = gv + base + (size_t)((j + 2) * 64 + sr) * DH + scb * 8;
            uint32_t kd = sb0 + bn * ABUFB + kdst0;
#pragma unroll
            for (int i = 0; i < 4; i++) cp16(kd + i * 16, ks + i * 8);
#pragma unroll
            for (int i = 0; i < 4; i++) cp16(kd + AK_BYTES + i * 16, vs + i * 8);
            cp_commit();
        }
    }
#undef ATTN_HALF

    // ---- epilogue: normalize, write fp16 ctx ----
#pragma unroll
    for (int mt = 0; mt < 2; mt++) {
        float s0 = acc[mt][0], s1 = acc[mt][1];
        s0 += __shfl_xor_sync(0xffffffffu, s0, 1);
        s0 += __shfl_xor_sync(0xffffffffu, s0, 2);
        s1 += __shfl_xor_sync(0xffffffffu, s1, 1);
        s1 += __shfl_xor_sync(0xffffffffu, s1, 2);
        float inv0 = 1.f / s0, inv1 = 1.f / s1;
        int r = q0 + wm + mt * 16 + q;
        __half* d0 = gctx + ((size_t)n_ * LQ + r) * HDIM + h_ * DH;
        __half* d1 = gctx + ((size_t)n_ * LQ + r + 8) * HDIM + h_ * DH;
#pragma unroll
        for (int nt = 0; nt < 8; nt++) {
            int d_ = nt * 8 + 2 * c4;
            *(__half2*)(d0 + d_) = __floats2half2_rn(O[mt][nt][0] * inv0,
                                                     O[mt][nt][1] * inv0);
            *(__half2*)(d1 + d_) = __floats2half2_rn(O[mt][nt][2] * inv1,
                                                     O[mt][nt][3] * inv1);
        }
    }
}

// ===========================================================================
extern "C" void kernel_launch(void* const* d_in, const int* in_sizes, int n_in,
                              void* d_out, int out_size)
{
    (void)in_sizes; (void)n_in; (void)out_size;
    const float* x  = (const float*)d_in[0];
    const float* Wq = (const float*)d_in[1];
    const float* bq = (const float*)d_in[2];
    const float* Wk = (const float*)d_in[3];
    const float* bk = (const float*)d_in[4];
    const float* Wv = (const float*)d_in[5];
    const float* bv = (const float*)d_in[6];
    const float* Wo = (const float*)d_in[7];
    const float* bo = (const float*)d_in[8];
    float* out = (float*)d_out;

    __half *pxh, *pwh, *pqkv, *pctxh;
    cudaGetSymbolAddress((void**)&pxh,   g_xh);
    cudaGetSymbolAddress((void**)&pwh,   g_wh);
    cudaGetSymbolAddress((void**)&pqkv,  g_qkv);
    cudaGetSymbolAddress((void**)&pctxh, g_ctxh);

    cudaFuncSetAttribute(gemm_tc<0>, cudaFuncAttributeMaxDynamicSharedMemorySize, GEMM_SMEM);
    cudaFuncSetAttribute(gemm_tc<1>, cudaFuncAttributeMaxDynamicSharedMemorySize, GEMM_SMEM);
    cudaFuncSetAttribute(attn_mma,   cudaFuncAttributeMaxDynamicSharedMemorySize, ATTN_SMEM);

    const int CONV_THREADS = (XN + 4 * WSZ) / 4;
    f2h_all<<<CONV_THREADS / 256, 256>>>(x, Wq, Wk, Wv, Wo, pxh, pwh);

    dim3 bb(128);
    dim3 gqkv(HDIM / 64, NLROWS / 128, 3);    // (12, 64, 3)
    gemm_tc<0><<<gqkv, bb, GEMM_SMEM>>>(pxh, pwh, bq, bk, bv, pqkv);

    dim3 ga(LQ / 128, NHTOT);                 // (32, 24)
    attn_mma<<<ga, dim3(128), ATTN_SMEM>>>(pqkv, pqkv + QKVS, pqkv + 2 * QKVS, pctxh);

    dim3 go(HDIM / 64, NLROWS / 128, 1);      // (12, 64)
    gemm_tc<1><<<go, bb, GEMM_SMEM>>>(pctxh, pwh + 3 * (size_t)WSZ, bo, bo, bo, out);
}

// round 15
// speedup vs baseline: 1.0424x; 1.0424x over previous
#include <cuda_runtime.h>
#include <cuda_fp16.h>
#include <math.h>
#include <cstdint>

#define NB    2
#define LQ    4096
#define NHEAD 12
#define DH    64
#define HDIM  768
#define NLROWS (NB*LQ)     // 8192
#define NHTOT  (NB*NHEAD)  // 24
#define QKVS  ((size_t)NHTOT * LQ * DH)
#define WSZ   (HDIM * HDIM)                // 589824
#define XN    (NLROWS * HDIM)              // 6291456

// Scratch (device globals: allocation-free rule)
__device__ __half g_xh [(size_t)XN];               // x in fp16
__device__ __half g_wh [4 * (size_t)WSZ];          // Wq(scaled),Wk,Wv,Wo fp16
__device__ __half g_qkv[3 * QKVS];                 // [qkv][nh][l][d] fp16
__device__ __half g_ctxh[(size_t)NLROWS * HDIM];   // attention output fp16

#define QSCALE (0.125f * 1.44269504088896340736f)  // 1/sqrt(D) * log2(e)

// ---------------------------------------------------------------------------
// helpers
// ---------------------------------------------------------------------------
__device__ __forceinline__ uint32_t smem_u32(const void* p) {
    uint32_t a;
    asm("{ .reg .u64 t; cvta.to.shared.u64 t, %1; cvt.u32.u64 %0, t; }"
        : "=r"(a) : "l"(p));
    return a;
}
__device__ __forceinline__ float ex2f(float x) {
    float r; asm("ex2.approx.ftz.f32 %0, %1;" : "=f"(r) : "f"(x)); return r;
}
__device__ __forceinline__ uint32_t h2pack(float lo, float hi) {
    uint32_t u;
    asm("cvt.rn.f16x2.f32 %0, %1, %2;" : "=r"(u) : "f"(hi), "f"(lo));
    return u;
}
__device__ __forceinline__ void mma16(float* c, const uint32_t* a, const uint32_t* b) {
    asm volatile(
        "mma.sync.aligned.m16n8k16.row.col.f32.f16.f16.f32 "
        "{%0,%1,%2,%3}, {%4,%5,%6,%7}, {%8,%9}, {%0,%1,%2,%3};"
        : "+f"(c[0]), "+f"(c[1]), "+f"(c[2]), "+f"(c[3])
        : "r"(a[0]), "r"(a[1]), "r"(a[2]), "r"(a[3]), "r"(b[0]), "r"(b[1]));
}
__device__ __forceinline__ void ldmx4(uint32_t* r, uint32_t addr) {
    asm volatile("ldmatrix.sync.aligned.m8n8.x4.shared.b16 {%0,%1,%2,%3}, [%4];"
        : "=r"(r[0]), "=r"(r[1]), "=r"(r[2]), "=r"(r[3]) : "r"(addr));
}
__device__ __forceinline__ void ldmx4t(uint32_t* r, uint32_t addr) {
    asm volatile("ldmatrix.sync.aligned.m8n8.x4.trans.shared.b16 {%0,%1,%2,%3}, [%4];"
        : "=r"(r[0]), "=r"(r[1]), "=r"(r[2]), "=r"(r[3]) : "r"(addr));
}
__device__ __forceinline__ void cp16(uint32_t dst, const void* src) {
    asm volatile("cp.async.cg.shared.global [%0], [%1], 16;"
        :: "r"(dst), "l"(src) : "memory");
}
__device__ __forceinline__ void cp_commit() {
    asm volatile("cp.async.commit_group;" ::: "memory");
}
template<int N> __device__ __forceinline__ void cp_wait() {
    asm volatile("cp.async.wait_group %0;" :: "n"(N) : "memory");
}

// ===========================================================================
// Fused fp32->fp16 convert of all 5 tensors in ONE launch.
// ===========================================================================
__global__ void f2h_all(
    const float* __restrict__ x,  const float* __restrict__ Wq,
    const float* __restrict__ Wk, const float* __restrict__ Wv,
    const float* __restrict__ Wo, __half* __restrict__ xh,
    __half* __restrict__ wh)
{
    size_t i = ((size_t)blockIdx.x * blockDim.x + threadIdx.x) * 4;
    const float* src; __half* dst; float sc = 1.0f; size_t off;
    if (i < (size_t)XN) {
        src = x; dst = xh; off = i;
    } else {
        size_t j = i - XN;
        int w = (int)(j / WSZ);
        off = j - (size_t)w * WSZ;
        dst = wh + (size_t)w * WSZ;
        src = (w == 0) ? Wq : (w == 1) ? Wk : (w == 2) ? Wv : Wo;
        if (w == 0) sc = QSCALE;
    }
    float4 v = *(const float4*)(src + off);
    *(__half2*)(dst + off)     = __floats2half2_rn(v.x * sc, v.y * sc);
    *(__half2*)(dst + off + 2) = __floats2half2_rn(v.z * sc, v.w * sc);
}

// ===========================================================================
// fp16 GEMM: C[M,768] = A[M,768] @ W[768,768] + bias.
// cp.async 3-stage ring (ONE barrier/iter, prefetch AFTER compute) +
// ldmatrix + m16n8k16. CTA: 256 thr (8 warps, 4m x 2n), tile 128x128,
// K-chunk 32. Smem/buf: A [128 rows][80B] + W [32 rows][272B].
// ===========================================================================
#define GA_BYTES (128 * 80)                 // 10240
#define GW_BYTES (32 * 272)                 // 8704
#define GBUFB    (GA_BYTES + GW_BYTES)      // 18944
#define GEMM_SMEM (3 * GBUFB)               // 56832

template<int MODE>
__global__ __launch_bounds__(256, 2) void gemm_tc(
    const __half* __restrict__ A, const __half* __restrict__ Whbase,
    const float* __restrict__ b0, const float* __restrict__ b1,
    const float* __restrict__ b2, void* __restrict__ outv)
{
    extern __shared__ char smc[];
    const uint32_t sb0 = smem_u32(smc);
    const int z = (MODE == 0) ? blockIdx.z : 0;
    const __half* W = Whbase + (size_t)z * WSZ;
    const float* bias = (z == 0) ? b0 : (z == 1) ? b1 : b2;
    const float bsc = (MODE == 0 && z == 0) ? QSCALE : 1.0f;

    const int tid = threadIdx.x;
    const int lane = tid & 31;
    const int q  = lane >> 2, c4 = lane & 3;
    const int wid = tid >> 5;
    const int wy = wid >> 1, wx = wid & 1;
    const int row0 = blockIdx.y << 7;
    const int col0 = blockIdx.x << 7;

    // cp.async staging roles (each thread: 2 A chunks + 2 W chunks)
    const int ar = tid & 127, ac = (tid >> 7) * 2;
    const int wr = tid & 31,  wc = (tid >> 5) * 2;
    const __half* asrc0 = A + (size_t)(row0 + ar) * HDIM + ac * 8;
    const __half* wsrc0 = W + (size_t)wr * HDIM + col0 + wc * 8;
    const uint32_t adst0 = ar * 80 + ac * 16;
    const uint32_t wdst0 = GA_BYTES + wr * 272 + wc * 16;

    // ldmatrix per-thread address pieces
    const uint32_t a_off = (uint32_t)((wy * 32 + (lane & 15)) * 80 + (lane >> 4) * 16);
    const uint32_t w_off = (uint32_t)(GA_BYTES + (lane & 15) * 272 +
                                      (wx * 64) * 2 + (lane >> 4) * 16);

    float C[2][8][4] = {};

    // pre-issue chunks 0 and 1 into buffers 0 and 1
#pragma unroll
    for (int c = 0; c < 2; c++) {
        uint32_t bb = sb0 + c * GBUFB;
        const __half* as = asrc0 + c * 32;
        const __half* ws = wsrc0 + (size_t)(c * 32) * HDIM;
        cp16(bb + adst0, as); cp16(bb + adst0 + 16, as + 8);
        cp16(bb + wdst0, ws); cp16(bb + wdst0 + 16, ws + 8);
        cp_commit();
    }

    int bcur = 0;
    for (int c = 0; c < 24; c++) {
        if (c < 23) cp_wait<1>(); else cp_wait<0>();
        __syncthreads();

        const uint32_t sb = sb0 + bcur * GBUFB;
#pragma unroll
        for (int s = 0; s < 2; s++) {
            uint32_t a[2][4];
            ldmx4(a[0], sb + a_off + s * 32);
            ldmx4(a[1], sb + a_off + 16 * 80 + s * 32);
#pragma unroll
            for (int nj = 0; nj < 4; nj++) {
                uint32_t b[4];
                ldmx4t(b, sb + w_off + (s * 16) * 272 + nj * 32);
                mma16(C[0][2*nj],   a[0], &b[0]);
                mma16(C[0][2*nj+1], a[0], &b[2]);
                mma16(C[1][2*nj],   a[1], &b[0]);
                mma16(C[1][2*nj+1], a[1], &b[2]);
            }
        }

        // issue chunk c+2 into buffer (bcur+2)%3 (readers finished: barrier above)
        if (c < 22) {
            int bn = bcur + 2; if (bn >= 3) bn -= 3;
            int k0 = (c + 2) * 32;
            uint32_t bb = sb0 + bn * GBUFB;
            const __half* as = asrc0 + k0;
            const __half* ws = wsrc0 + (size_t)k0 * HDIM;
            cp16(bb + adst0, as); cp16(bb + adst0 + 16, as + 8);
            cp16(bb + wdst0, ws); cp16(bb + wdst0 + 16, ws + 8);
            cp_commit();
        }
        if (++bcur == 3) bcur = 0;
    }

    // ---- epilogue ----
#pragma unroll
    for (int mt = 0; mt < 2; mt++) {
#pragma unroll
        for (int nt = 0; nt < 8; nt++) {
            int r  = row0 + wy * 32 + mt * 16 + q;
            int cc = col0 + wx * 64 + nt * 8 + 2 * c4;
            float2 bv = *(const float2*)(bias + cc);
            float o00 = C[mt][nt][0] + bv.x * bsc;
            float o01 = C[mt][nt][1] + bv.y * bsc;
            float o10 = C[mt][nt][2] + bv.x * bsc;
            float o11 = C[mt][nt][3] + bv.y * bsc;
            if (MODE == 0) {
                __half* dst = (__half*)outv + (size_t)z * QKVS;
                int h_ = cc >> 6, d_ = cc & 63;
                int n0 = r >> 12, l0 = r & 4095;
                int n1 = (r + 8) >> 12, l1 = (r + 8) & 4095;
                *(__half2*)(dst + ((size_t)(n0 * NHEAD + h_) * LQ + l0) * DH + d_) =
                    __floats2half2_rn(o00, o01);
                *(__half2*)(dst + ((size_t)(n1 * NHEAD + h_) * LQ + l1) * DH + d_) =
                    __floats2half2_rn(o10, o11);
            } else {
                float* dst = (float*)outv;
                *(float2*)(dst + (size_t)r * HDIM + cc) = make_float2(o00, o01);
                *(float2*)(dst + (size_t)(r + 8) * HDIM + cc) = make_float2(o10, o11);
            }
        }
    }
}

// ===========================================================================
// fp16 flash attention. cp.async 3-stage ring (ONE barrier/iter) + ldmatrix.
// CTA: 128 thr (4 warps), Q tile 128 (32 rows/warp), key tiles 64 in two
// 32-key halves. P stays in registers (S C-frags -> PV A-frags).
// Smem/buf: K [64 rows][144B] + V [64 rows][144B]; 3 buffers.
// Q is staged through buffer 2 (free: tile-2 cp lands after Qf preload).
// ===========================================================================
#define AK_BYTES (64 * 144)                  // 9216
#define ABUFB    (2 * AK_BYTES)              // 18432
#define ATTN_SMEM (3 * ABUFB)                // 55296

__global__ __launch_bounds__(128) void attn_mma(
    const __half* __restrict__ gq, const __half* __restrict__ gk,
    const __half* __restrict__ gv, __half* __restrict__ gctx)
{
    extern __shared__ char smc[];
    const uint32_t sb0 = smem_u32(smc);
    const int tid = threadIdx.x;
    const int lane = tid & 31;
    const int q  = lane >> 2, c4 = lane & 3;
    const int wid = tid >> 5;
    const int wm = wid * 32;
    const int nh = blockIdx.y;
    const int n_ = nh / NHEAD, h_ = nh % NHEAD;
    const int q0 = blockIdx.x << 7;
    const size_t base = (size_t)nh * LQ * DH;

    // ldmatrix address pieces
    const uint32_t krow8  = (uint32_t)((lane & 7) + (lane >> 4) * 8);   // K (non-trans B)
    const uint32_t koff16 = (uint32_t)(((lane >> 3) & 1) * 16);
    const uint32_t vrow   = (uint32_t)(lane & 15);                      // V (trans B) / Q (A)
    const uint32_t voff16 = (uint32_t)((lane >> 4) * 16);

    // cp.async staging: thread -> 4 K chunks + 4 V chunks
    const int sr = tid & 63, scb = (tid >> 6) * 4;
    const uint32_t kdst0 = sr * 144 + scb * 16;

    // ---- stage Q via cp.async into buffer-2 region, preload Q fragments ----
    {
        const __half* src = gq + base + (size_t)(q0 + tid) * DH;
        uint32_t dst = sb0 + 2 * ABUFB + tid * 144;
#pragma unroll
        for (int i = 0; i < 8; i++) cp16(dst + i * 16, src + i * 8);
        cp_commit();
        cp_wait<0>();
    }
    __syncthreads();
    uint32_t Qf[2][4][4];
#pragma unroll
    for (int mt = 0; mt < 2; mt++)
#pragma unroll
        for (int s = 0; s < 4; s++)
            ldmx4(Qf[mt][s], sb0 + 2 * ABUFB + (wm + mt * 16 + vrow) * 144 +
                             s * 32 + voff16);
    __syncthreads();   // all warps done reading Q before tile-2 cp overwrites

    // pre-issue tiles 0 and 1 into buffers 0 and 1
#pragma unroll
    for (int t = 0; t < 2; t++) {
        const __half* ks = gk + base + (size_t)(t * 64 + sr) * DH + scb * 8;
        const __half* vs = gv + base + (size_t)(t * 64 + sr) * DH + scb * 8;
        uint32_t kd = sb0 + t * ABUFB + kdst0;
#pragma unroll
        for (int i = 0; i < 4; i++) cp16(kd + i * 16, ks + i * 8);
#pragma unroll
        for (int i = 0; i < 4; i++) cp16(kd + AK_BYTES + i * 16, vs + i * 8);
        cp_commit();
    }

#define ATTN_HALF(hh)                                                         \
    {                                                                         \
        float S[2][4][4] = {};                                                \
        _Pragma("unroll")                                                     \
        for (int s = 0; s < 4; s++) {                                         \
            _Pragma("unroll")                                                 \
            for (int g = 0; g < 2; g++) {                                     \
                uint32_t t[4];                                                \
                ldmx4(t, kb + ((hh)*32 + g*16 + krow8) * 144 + s*32 + koff16);\
                mma16(S[0][2*g],   Qf[0][s], &t[0]);                          \
                mma16(S[0][2*g+1], Qf[0][s], &t[2]);                          \
                mma16(S[1][2*g],   Qf[1][s], &t[0]);                          \
                mma16(S[1][2*g+1], Qf[1][s], &t[2]);                          \
            }                                                                 \
        }                                                                     \
        uint32_t P[2][2][4];                                                  \
        _Pragma("unroll")                                                     \
        for (int mt = 0; mt < 2; mt++) {                                      \
            _Pragma("unroll")                                                 \
            for (int ks = 0; ks < 2; ks++) {                                  \
                float e0 = ex2f(S[mt][2*ks][0]),  e1 = ex2f(S[mt][2*ks][1]);  \
                float e2 = ex2f(S[mt][2*ks][2]),  e3 = ex2f(S[mt][2*ks][3]);  \
                float f0 = ex2f(S[mt][2*ks+1][0]), f1 = ex2f(S[mt][2*ks+1][1]);\
                float f2 = ex2f(S[mt][2*ks+1][2]), f3 = ex2f(S[mt][2*ks+1][3]);\
                acc[mt][0] += (e0 + e1) + (f0 + f1);                          \
                acc[mt][1] += (e2 + e3) + (f2 + f3);                          \
                P[mt][ks][0] = h2pack(e0, e1);                                \
                P[mt][ks][1] = h2pack(e2, e3);                                \
                P[mt][ks][2] = h2pack(f0, f1);                                \
                P[mt][ks][3] = h2pack(f2, f3);                                \
            }                                                                 \
        }                                                                     \
        _Pragma("unroll")                                                     \
        for (int ks = 0; ks < 2; ks++) {                                      \
            _Pragma("unroll")                                                 \
            for (int nj = 0; nj < 4; nj++) {                                  \
                uint32_t t[4];                                                \
                ldmx4t(t, vb + ((hh)*32 + ks*16 + vrow) * 144 + nj*32 + voff16);\
                mma16(O[0][2*nj],   P[0][ks], &t[0]);                         \
                mma16(O[0][2*nj+1], P[0][ks], &t[2]);                         \
                mma16(O[1][2*nj],   P[1][ks], &t[0]);                         \
                mma16(O[1][2*nj+1], P[1][ks], &t[2]);                         \
            }                                                                 \
        }                                                                     \
    }

    float O[2][8][4] = {};
    float acc[2][2] = {};

    for (int j = 0; j < LQ / 64; j++) {
        if (j < LQ / 64 - 1) cp_wait<1>(); else cp_wait<0>();
        __syncthreads();

        const uint32_t kb = sb0 + (j % 3) * ABUFB;
        const uint32_t vb = kb + AK_BYTES;
        ATTN_HALF(0)
        ATTN_HALF(1)

        // issue tile j+2 into buffer (j+2)%3 (safe: barrier above)
        if (j < LQ / 64 - 2) {
            int bn = (j + 2) % 3;
            const __half* ks = gk + base + (size_t)((j + 2) * 64 + sr) * DH + scb * 8;
            const __half* vs = gv + base + (size_t)((j + 2) * 64 + sr) * DH + scb * 8;
            uint32_t kd = sb0 + bn * ABUFB + kdst0;
#pragma unroll
            for (int i = 0; i < 4; i++) cp16(kd + i * 16, ks + i * 8);
#pragma unroll
            for (int i = 0; i < 4; i++) cp16(kd + AK_BYTES + i * 16, vs + i * 8);
            cp_commit();
        }
    }
#undef ATTN_HALF

    // ---- epilogue: normalize, write fp16 ctx ----
#pragma unroll
    for (int mt = 0; mt < 2; mt++) {
        float s0 = acc[mt][0], s1 = acc[mt][1];
        s0 += __shfl_xor_sync(0xffffffffu, s0, 1);
        s0 += __shfl_xor_sync(0xffffffffu, s0, 2);
        s1 += __shfl_xor_sync(0xffffffffu, s1, 1);
        s1 += __shfl_xor_sync(0xffffffffu, s1, 2);
        float inv0 = 1.f / s0, inv1 = 1.f / s1;
        int r = q0 + wm + mt * 16 + q;
        __half* d0 = gctx + ((size_t)n_ * LQ + r) * HDIM + h_ * DH;
        __half* d1 = gctx + ((size_t)n_ * LQ + r + 8) * HDIM + h_ * DH;
#pragma unroll
        for (int nt = 0; nt < 8; nt++) {
            int d_ = nt * 8 + 2 * c4;
            *(__half2*)(d0 + d_) = __floats2half2_rn(O[mt][nt][0] * inv0,
                                                     O[mt][nt][1] * inv0);
            *(__half2*)(d1 + d_) = __floats2half2_rn(O[mt][nt][2] * inv1,
                                                     O[mt][nt][3] * inv1);
        }
    }
}

// ===========================================================================
extern "C" void kernel_launch(void* const* d_in, const int* in_sizes, int n_in,
                              void* d_out, int out_size)
{
    (void)in_sizes; (void)n_in; (void)out_size;
    const float* x  = (const float*)d_in[0];
    const float* Wq = (const float*)d_in[1];
    const float* bq = (const float*)d_in[2];
    const float* Wk = (const float*)d_in[3];
    const float* bk = (const float*)d_in[4];
    const float* Wv = (const float*)d_in[5];
    const float* bv = (const float*)d_in[6];
    const float* Wo = (const float*)d_in[7];
    const float* bo = (const float*)d_in[8];
    float* out = (float*)d_out;

    __half *pxh, *pwh, *pqkv, *pctxh;
    cudaGetSymbolAddress((void**)&pxh,   g_xh);
    cudaGetSymbolAddress((void**)&pwh,   g_wh);
    cudaGetSymbolAddress((void**)&pqkv,  g_qkv);
    cudaGetSymbolAddress((void**)&pctxh, g_ctxh);

    cudaFuncSetAttribute(gemm_tc<0>, cudaFuncAttributeMaxDynamicSharedMemorySize, GEMM_SMEM);
    cudaFuncSetAttribute(gemm_tc<1>, cudaFuncAttributeMaxDynamicSharedMemorySize, GEMM_SMEM);
    cudaFuncSetAttribute(attn_mma,   cudaFuncAttributeMaxDynamicSharedMemorySize, ATTN_SMEM);

    const int CONV_THREADS = (XN + 4 * WSZ) / 4;
    f2h_all<<<CONV_THREADS / 256, 256>>>(x, Wq, Wk, Wv, Wo, pxh, pwh);

    dim3 bb(256);
    dim3 gqkv(HDIM / 128, NLROWS / 128, 3);   // (6, 64, 3)
    gemm_tc<0><<<gqkv, bb, GEMM_SMEM>>>(pxh, pwh, bq, bk, bv, pqkv);

    dim3 ga(LQ / 128, NHTOT);                 // (32, 24)
    attn_mma<<<ga, dim3(128), ATTN_SMEM>>>(pqkv, pqkv + QKVS, pqkv + 2 * QKVS, pctxh);

    dim3 go(HDIM / 128, NLROWS / 128, 1);     // (6, 64)
    gemm_tc<1><<<go, bb, GEMM_SMEM>>>(pctxh, pwh + 3 * (size_t)WSZ, bo, bo, bo, out);
}